// round 2
// baseline (speedup 1.0000x reference)
#include <cuda_runtime.h>

#define NN 2048
#define TT 32
#define FIN 5
#define HH 64
#define G4 256
#define GH 16
#define NW (NN/32)

// ---------------- scratch (static device allocations) ----------------
__device__ float    g_h0[NN*TT*HH];     // layer0 hidden sequence (16 MB)
__device__ float    g_xlast[NN*HH];     // layer1 final hidden
__device__ unsigned g_adj[NN*NW];       // adj bits: g_adj[m*64 + n/32], bit n%32
__device__ float    g_h1[NN*GH];
__device__ float    g_hs1[NN];
__device__ float    g_hd1[NN];
__device__ float    g_out1[NN*GH];
__device__ float    g_hs2[NN];
__device__ float    g_hd2[NN];
__device__ float    g_hfc[NN];
__device__ float    g_cbias;

__device__ __forceinline__ float fsig(float x)  { return 1.0f/(1.0f+__expf(-x)); }
__device__ __forceinline__ float ftanh(float x) { return 1.0f - 2.0f/(__expf(2.0f*x)+1.0f); }
__device__ __forceinline__ float lrelu(float x) { return x > 0.0f ? x : 0.2f*x; }

__device__ __forceinline__ float wredmax(float v){
    #pragma unroll
    for (int o = 16; o; o >>= 1) v = fmaxf(v, __shfl_xor_sync(0xffffffffu, v, o));
    return v;
}
__device__ __forceinline__ float wredsum(float v){
    #pragma unroll
    for (int o = 16; o; o >>= 1) v += __shfl_xor_sync(0xffffffffu, v, o);
    return v;
}

// ---------------- LSTM layer 0: (N,T,5) -> g_h0 (N,T,64) ----------------
// block = 256 threads, 16 nodes/block. thread: u = tid&63 (hidden unit),
// sub = tid>>6; handles nodes sub*4 .. sub*4+3. Weights packed float4 per
// (k, u) = (w_i, w_f, w_g, w_o) so each LDS.128 feeds 4 gate FMAs.
__global__ void lstm0_kernel(const float* __restrict__ inp,
                             const float* __restrict__ wih,
                             const float* __restrict__ whh,
                             const float* __restrict__ bih,
                             const float* __restrict__ bhh)
{
    extern __shared__ float sm[];
    float4* wih_s = (float4*)sm;               // [5][64] float4
    float4* whh_s = wih_s + FIN*64;            // [64][64] float4
    float*  bsum  = (float*)(whh_s + 64*64);   // [256]
    float*  hbuf  = bsum + G4;                 // [2][16][64]
    float*  xs    = hbuf + 2*16*HH;            // [16][32][5]

    const int tid = threadIdx.x;
    const int n0  = blockIdx.x * 16;

    for (int i = tid; i < FIN*64; i += 256) {
        int k = i >> 6, u = i & 63;
        wih_s[i] = make_float4(wih[u*FIN+k], wih[(64+u)*FIN+k],
                               wih[(128+u)*FIN+k], wih[(192+u)*FIN+k]);
    }
    for (int i = tid; i < 64*64; i += 256) {
        int k = i >> 6, u = i & 63;
        whh_s[i] = make_float4(whh[u*HH+k], whh[(64+u)*HH+k],
                               whh[(128+u)*HH+k], whh[(192+u)*HH+k]);
    }
    for (int i = tid; i < G4; i += 256) bsum[i] = bih[i] + bhh[i];
    for (int i = tid; i < 2*16*HH; i += 256) hbuf[i] = 0.0f;
    for (int i = tid; i < 16*TT*FIN; i += 256) xs[i] = inp[n0*TT*FIN + i];
    __syncthreads();

    const int u = tid & 63, sub = tid >> 6;
    float c[4] = {0.f, 0.f, 0.f, 0.f};

    for (int t = 0; t < TT; t++) {
        const int cur = (t & 1) * 16*HH;
        const int nxt = ((t & 1) ^ 1) * 16*HH;
        float a0[4] = {0,0,0,0}, a1[4] = {0,0,0,0}, a2[4] = {0,0,0,0}, a3[4] = {0,0,0,0};

        #pragma unroll
        for (int k = 0; k < FIN; k++) {
            float4 w = wih_s[k*64 + u];
            #pragma unroll
            for (int q = 0; q < 4; q++) {
                float xv = xs[(sub*4+q)*TT*FIN + t*FIN + k];
                a0[q] += w.x*xv; a1[q] += w.y*xv; a2[q] += w.z*xv; a3[q] += w.w*xv;
            }
        }
        #pragma unroll
        for (int k4 = 0; k4 < 16; k4++) {
            float4 w0 = whh_s[(k4*4+0)*64+u];
            float4 w1 = whh_s[(k4*4+1)*64+u];
            float4 w2 = whh_s[(k4*4+2)*64+u];
            float4 w3 = whh_s[(k4*4+3)*64+u];
            #pragma unroll
            for (int q = 0; q < 4; q++) {
                float4 hv = *(const float4*)&hbuf[cur + (sub*4+q)*HH + k4*4];
                a0[q] += w0.x*hv.x + w1.x*hv.y + w2.x*hv.z + w3.x*hv.w;
                a1[q] += w0.y*hv.x + w1.y*hv.y + w2.y*hv.z + w3.y*hv.w;
                a2[q] += w0.z*hv.x + w1.z*hv.y + w2.z*hv.z + w3.z*hv.w;
                a3[q] += w0.w*hv.x + w1.w*hv.y + w2.w*hv.z + w3.w*hv.w;
            }
        }
        #pragma unroll
        for (int q = 0; q < 4; q++) {
            int nl = sub*4 + q;
            float gi = fsig (a0[q] + bsum[u]);
            float gf = fsig (a1[q] + bsum[64+u]);
            float gg = ftanh(a2[q] + bsum[128+u]);
            float go = fsig (a3[q] + bsum[192+u]);
            c[q] = gf*c[q] + gi*gg;
            float hv = go * ftanh(c[q]);
            hbuf[nxt + nl*HH + u] = hv;
            g_h0[(n0+nl)*TT*HH + t*HH + u] = hv;
        }
        __syncthreads();
    }
}

// ---------------- LSTM layer 1: g_h0 -> g_xlast (N,64) ----------------
__global__ void lstm1_kernel(const float* __restrict__ wih,
                             const float* __restrict__ whh,
                             const float* __restrict__ bih,
                             const float* __restrict__ bhh)
{
    extern __shared__ float sm[];
    float4* wih_s = (float4*)sm;               // [64][64] float4
    float4* whh_s = wih_s + 64*64;             // [64][64] float4
    float*  bsum  = (float*)(whh_s + 64*64);
    float*  hbuf  = bsum + G4;                 // [2][16][64]
    float*  xs    = hbuf + 2*16*HH;            // [16][64]

    const int tid = threadIdx.x;
    const int n0  = blockIdx.x * 16;

    for (int i = tid; i < 64*64; i += 256) {
        int k = i >> 6, u = i & 63;
        wih_s[i] = make_float4(wih[u*HH+k], wih[(64+u)*HH+k],
                               wih[(128+u)*HH+k], wih[(192+u)*HH+k]);
        whh_s[i] = make_float4(whh[u*HH+k], whh[(64+u)*HH+k],
                               whh[(128+u)*HH+k], whh[(192+u)*HH+k]);
    }
    for (int i = tid; i < G4; i += 256) bsum[i] = bih[i] + bhh[i];
    for (int i = tid; i < 2*16*HH; i += 256) hbuf[i] = 0.0f;
    __syncthreads();

    const int u = tid & 63, sub = tid >> 6;
    float c[4] = {0.f, 0.f, 0.f, 0.f};

    for (int t = 0; t < TT; t++) {
        // stage this step's inputs (layer-0 h)
        for (int i = tid; i < 16*HH; i += 256) {
            int nl = i >> 6, k = i & 63;
            xs[i] = g_h0[(n0+nl)*TT*HH + t*HH + k];
        }
        __syncthreads();

        const int cur = (t & 1) * 16*HH;
        const int nxt = ((t & 1) ^ 1) * 16*HH;
        float a0[4] = {0,0,0,0}, a1[4] = {0,0,0,0}, a2[4] = {0,0,0,0}, a3[4] = {0,0,0,0};

        #pragma unroll
        for (int k4 = 0; k4 < 16; k4++) {
            float4 w0 = wih_s[(k4*4+0)*64+u];
            float4 w1 = wih_s[(k4*4+1)*64+u];
            float4 w2 = wih_s[(k4*4+2)*64+u];
            float4 w3 = wih_s[(k4*4+3)*64+u];
            #pragma unroll
            for (int q = 0; q < 4; q++) {
                float4 xv = *(const float4*)&xs[(sub*4+q)*HH + k4*4];
                a0[q] += w0.x*xv.x + w1.x*xv.y + w2.x*xv.z + w3.x*xv.w;
                a1[q] += w0.y*xv.x + w1.y*xv.y + w2.y*xv.z + w3.y*xv.w;
                a2[q] += w0.z*xv.x + w1.z*xv.y + w2.z*xv.z + w3.z*xv.w;
                a3[q] += w0.w*xv.x + w1.w*xv.y + w2.w*xv.z + w3.w*xv.w;
            }
        }
        #pragma unroll
        for (int k4 = 0; k4 < 16; k4++) {
            float4 w0 = whh_s[(k4*4+0)*64+u];
            float4 w1 = whh_s[(k4*4+1)*64+u];
            float4 w2 = whh_s[(k4*4+2)*64+u];
            float4 w3 = whh_s[(k4*4+3)*64+u];
            #pragma unroll
            for (int q = 0; q < 4; q++) {
                float4 hv = *(const float4*)&hbuf[cur + (sub*4+q)*HH + k4*4];
                a0[q] += w0.x*hv.x + w1.x*hv.y + w2.x*hv.z + w3.x*hv.w;
                a1[q] += w0.y*hv.x + w1.y*hv.y + w2.y*hv.z + w3.y*hv.w;
                a2[q] += w0.z*hv.x + w1.z*hv.y + w2.z*hv.z + w3.z*hv.w;
                a3[q] += w0.w*hv.x + w1.w*hv.y + w2.w*hv.z + w3.w*hv.w;
            }
        }
        #pragma unroll
        for (int q = 0; q < 4; q++) {
            int nl = sub*4 + q;
            float gi = fsig (a0[q] + bsum[u]);
            float gf = fsig (a1[q] + bsum[64+u]);
            float gg = ftanh(a2[q] + bsum[128+u]);
            float go = fsig (a3[q] + bsum[192+u]);
            c[q] = gf*c[q] + gi*gg;
            float hv = go * ftanh(c[q]);
            hbuf[nxt + nl*HH + u] = hv;
            if (t == TT-1) g_xlast[(n0+nl)*HH + u] = hv;
        }
        __syncthreads();
    }
}

// ---------------- adjacency bitmask ----------------
// adj[n][m] = (rel_mask[n][m]==0) || (n==m). softmax over masked -1e9 entries
// underflows to exactly 0 in fp32 (margin ~1e9 vs 87), so ws>0 == this mask.
// Bits stored column-major: g_adj[m*64 + n/32] bit (n%32).
__global__ void adj_kernel(const float* __restrict__ relm)
{
    __shared__ int s[32][33];
    const int tid = threadIdx.x;
    const int m0 = blockIdx.x * 32, n0 = blockIdx.y * 32;
    {
        int nl = tid >> 5, ml = tid & 31;
        float v = relm[(size_t)(n0+nl)*NN + (m0+ml)];
        s[nl][ml] = (v == 0.0f) || ((n0+nl) == (m0+ml));
    }
    __syncthreads();
    {
        int mcol = tid >> 5, nlane = tid & 31;
        unsigned w = __ballot_sync(0xffffffffu, s[nlane][mcol] != 0);
        if (nlane == 0) g_adj[(m0+mcol)*NW + blockIdx.y] = w;
    }
}

// ---------------- GAT1 prep: h1 = x@W1, hs1 = h1@a_s, hd1 = h1@a_d ----------------
__global__ void prep1_kernel(const float* __restrict__ W,
                             const float* __restrict__ as,
                             const float* __restrict__ ad)
{
    __shared__ float Ws[64*GH], ass[GH], ads[GH];
    const int tid = threadIdx.x;
    for (int i = tid; i < 64*GH; i += 256) Ws[i] = W[i];
    if (tid < GH) { ass[tid] = as[tid]; ads[tid] = ad[tid]; }
    __syncthreads();

    const int n = blockIdx.x*256 + tid;
    float xv[64];
    const float4* xr = (const float4*)&g_xlast[n*HH];
    #pragma unroll
    for (int i = 0; i < 16; i++) {
        float4 tv = xr[i];
        xv[4*i] = tv.x; xv[4*i+1] = tv.y; xv[4*i+2] = tv.z; xv[4*i+3] = tv.w;
    }
    float hs = 0.f, hd = 0.f;
    #pragma unroll
    for (int j = 0; j < GH; j++) {
        float sj = 0.f;
        #pragma unroll
        for (int k = 0; k < 64; k++) sj += xv[k] * Ws[k*GH + j];
        g_h1[n*GH + j] = sj;
        hs += sj * ass[j]; hd += sj * ads[j];
    }
    g_hs1[n] = hs; g_hd1[n] = hd;
}

// ---------------- GAT1 aggregate: out1[m] = relu(sum_n softmax * h1[n] + b1) ----------------
__global__ void gat1_agg_kernel(const float* __restrict__ b1)
{
    const int lane = threadIdx.x & 31;
    const int m = blockIdx.x*8 + (threadIdx.x >> 5);
    const float hdm = g_hd1[m];
    const unsigned* row = &g_adj[m*NW];

    float mx = -3.4e38f;
    for (int it = 0; it < NW; it++) {
        unsigned w = row[it];
        if ((w >> lane) & 1u) mx = fmaxf(mx, g_hs1[it*32 + lane]);
    }
    mx = wredmax(mx);
    const float emax = lrelu(mx + hdm);

    float s = 0.f;
    float acc[GH];
    #pragma unroll
    for (int j = 0; j < GH; j++) acc[j] = 0.f;

    for (int it = 0; it < NW; it++) {
        unsigned w = row[it];
        if ((w >> lane) & 1u) {
            int n = it*32 + lane;
            float p = __expf(lrelu(g_hs1[n] + hdm) - emax);
            s += p;
            const float4* hr = (const float4*)&g_h1[n*GH];
            float hv[GH];
            #pragma unroll
            for (int i = 0; i < 4; i++) {
                float4 tv = hr[i];
                hv[4*i] = tv.x; hv[4*i+1] = tv.y; hv[4*i+2] = tv.z; hv[4*i+3] = tv.w;
            }
            #pragma unroll
            for (int j = 0; j < GH; j++) acc[j] += p * hv[j];
        }
    }
    s = wredsum(s);
    #pragma unroll
    for (int j = 0; j < GH; j++) acc[j] = wredsum(acc[j]);

    if (lane == 0) {
        float inv = 1.0f / s;
        #pragma unroll
        for (int j = 0; j < GH; j++)
            g_out1[m*GH + j] = fmaxf(acc[j]*inv + b1[j], 0.0f);
    }
}

// ---------------- GAT2 prep (folds fc): hs2/hd2/hfc per node + cbias ----------------
__global__ void prep2_kernel(const float* __restrict__ W2,
                             const float* __restrict__ as2,
                             const float* __restrict__ ad2,
                             const float* __restrict__ b2,
                             const float* __restrict__ fcw,
                             const float* __restrict__ fcb)
{
    __shared__ float Ws[GH*HH], as_s[HH], ad_s[HH], fc_s[HH];
    const int tid = threadIdx.x;
    for (int i = tid; i < GH*HH; i += 256) Ws[i] = W2[i];
    if (tid < HH) { as_s[tid] = as2[tid]; ad_s[tid] = ad2[tid]; fc_s[tid] = fcw[tid]; }
    __syncthreads();

    const int n = blockIdx.x*256 + tid;
    float o1[GH];
    const float4* orr = (const float4*)&g_out1[n*GH];
    #pragma unroll
    for (int i = 0; i < 4; i++) {
        float4 tv = orr[i];
        o1[4*i] = tv.x; o1[4*i+1] = tv.y; o1[4*i+2] = tv.z; o1[4*i+3] = tv.w;
    }
    float hs = 0.f, hd = 0.f, hf = 0.f;
    #pragma unroll
    for (int j = 0; j < HH; j++) {
        float hj = 0.f;
        #pragma unroll
        for (int k = 0; k < GH; k++) hj += o1[k] * Ws[k*HH + j];
        hs += hj * as_s[j]; hd += hj * ad_s[j]; hf += hj * fc_s[j];
    }
    g_hs2[n] = hs; g_hd2[n] = hd; g_hfc[n] = hf;

    if (n == 0) {
        float cb = fcb[0];
        for (int j = 0; j < HH; j++) cb += b2[j] * fcw[j];
        g_cbias = cb;
    }
}

// ---------------- GAT2 aggregate + fc: out[m] = leaky(sum alpha*hfc / sum + cbias) ----------------
__global__ void gat2_agg_kernel(float* __restrict__ out)
{
    const int lane = threadIdx.x & 31;
    const int m = blockIdx.x*8 + (threadIdx.x >> 5);
    const float hdm = g_hd2[m];
    const unsigned* row = &g_adj[m*NW];

    float mx = -3.4e38f;
    for (int it = 0; it < NW; it++) {
        unsigned w = row[it];
        if ((w >> lane) & 1u) mx = fmaxf(mx, g_hs2[it*32 + lane]);
    }
    mx = wredmax(mx);
    const float emax = lrelu(mx + hdm);

    float s = 0.f, a = 0.f;
    for (int it = 0; it < NW; it++) {
        unsigned w = row[it];
        if ((w >> lane) & 1u) {
            int n = it*32 + lane;
            float p = __expf(lrelu(g_hs2[n] + hdm) - emax);
            s += p;
            a += p * g_hfc[n];
        }
    }
    s = wredsum(s);
    a = wredsum(a);
    if (lane == 0) out[m] = lrelu(a/s + g_cbias);
}

// ---------------- launch ----------------
extern "C" void kernel_launch(void* const* d_in, const int* in_sizes, int n_in,
                              void* d_out, int out_size)
{
    const float* inputs = (const float*)d_in[0];
    // d_in[1] relation, d_in[3] rel_w_W, d_in[4] rel_w_b: unused (adj shortcut)
    const float* relm   = (const float*)d_in[2];
    const float* w_ih0  = (const float*)d_in[5];
    const float* w_hh0  = (const float*)d_in[6];
    const float* b_ih0  = (const float*)d_in[7];
    const float* b_hh0  = (const float*)d_in[8];
    const float* w_ih1  = (const float*)d_in[9];
    const float* w_hh1  = (const float*)d_in[10];
    const float* b_ih1  = (const float*)d_in[11];
    const float* b_hh1  = (const float*)d_in[12];
    const float* gat1_W  = (const float*)d_in[13];
    const float* gat1_as = (const float*)d_in[14];
    const float* gat1_ad = (const float*)d_in[15];
    const float* gat1_b  = (const float*)d_in[16];
    const float* gat2_W  = (const float*)d_in[17];
    const float* gat2_as = (const float*)d_in[18];
    const float* gat2_ad = (const float*)d_in[19];
    const float* gat2_b  = (const float*)d_in[20];
    const float* fc_W    = (const float*)d_in[21];
    const float* fc_b    = (const float*)d_in[22];
    float* out = (float*)d_out;

    const int smem0 = (FIN*64*4 + 64*64*4 + G4 + 2*16*HH + 16*TT*FIN) * 4; // 90112 B
    const int smem1 = (64*64*4 + 64*64*4 + G4 + 2*16*HH + 16*HH) * 4;      // 144384 B
    cudaFuncSetAttribute(lstm0_kernel, cudaFuncAttributeMaxDynamicSharedMemorySize, smem0);
    cudaFuncSetAttribute(lstm1_kernel, cudaFuncAttributeMaxDynamicSharedMemorySize, smem1);

    lstm0_kernel<<<NN/16, 256, smem0>>>(inputs, w_ih0, w_hh0, b_ih0, b_hh0);
    lstm1_kernel<<<NN/16, 256, smem1>>>(w_ih1, w_hh1, b_ih1, b_hh1);
    adj_kernel<<<dim3(NN/32, NN/32), 1024>>>(relm);
    prep1_kernel<<<NN/256, 256>>>(gat1_W, gat1_as, gat1_ad);
    gat1_agg_kernel<<<NN/8, 256>>>(gat1_b);
    prep2_kernel<<<NN/256, 256>>>(gat2_W, gat2_as, gat2_ad, gat2_b, fc_W, fc_b);
    gat2_agg_kernel<<<NN/8, 256>>>(out);
}

// round 5
// speedup vs baseline: 1.0630x; 1.0630x over previous
#include <cuda_runtime.h>

#define NN 2048
#define TT 32
#define FIN 5
#define HH 64
#define GH 16
#define NW (NN/32)

// ---------------- scratch ----------------
__device__ float    g_xlast[NN*HH];
__device__ unsigned g_adj[NN*NW];
__device__ float    g_h1[NN*GH];
__device__ float    g_hs1[NN];
__device__ float    g_hd1[NN];
__device__ float    g_out1[NN*GH];
__device__ float    g_hs2[NN];
__device__ float    g_hd2[NN];
__device__ float    g_hfc[NN];
__device__ float    g_cbias;

__device__ __forceinline__ float fsig(float x)  { return 1.0f/(1.0f+__expf(-x)); }
__device__ __forceinline__ float ftanh(float x) { return 1.0f - 2.0f/(__expf(2.0f*x)+1.0f); }
__device__ __forceinline__ float lrelu(float x) { return x > 0.0f ? x : 0.2f*x; }

__device__ __forceinline__ float wredmax(float v){
    #pragma unroll
    for (int o = 16; o; o >>= 1) v = fmaxf(v, __shfl_xor_sync(0xffffffffu, v, o));
    return v;
}
__device__ __forceinline__ float wredsum(float v){
    #pragma unroll
    for (int o = 16; o; o >>= 1) v += __shfl_xor_sync(0xffffffffu, v, o);
    return v;
}

// packed fp32x2 FMA: d.lo += a.lo*b.lo ; d.hi += a.hi*b.hi
__device__ __forceinline__ void ffma2(unsigned long long &d,
                                      unsigned long long a,
                                      unsigned long long b){
    asm("fma.rn.f32x2 %0, %1, %2, %0;" : "+l"(d) : "l"(a), "l"(b));
}
__device__ __forceinline__ float2 unpk(unsigned long long v){
    float2 r; asm("mov.b64 {%0, %1}, %2;" : "=f"(r.x), "=f"(r.y) : "l"(v));
    return r;
}

// 64-k GEMM accumulate: acc[g][q] (f32x2, even/odd-k partials) +=
//   sum_k H[node(q)][k] * W[g][u][k].   W packed [k4][g][u] as float4(k0..k3).
__device__ __forceinline__ void gemm64(unsigned long long acc[4][8],
                                       const float4* __restrict__ W,
                                       const float*  __restrict__ H,
                                       int u, int sub)
{
    const ulonglong2* Wu = (const ulonglong2*)W;
    #pragma unroll 4
    for (int k4 = 0; k4 < 16; k4++) {
        ulonglong2 w0 = Wu[k4*256 +   0 + u];
        ulonglong2 w1 = Wu[k4*256 +  64 + u];
        ulonglong2 w2 = Wu[k4*256 + 128 + u];
        ulonglong2 w3 = Wu[k4*256 + 192 + u];
        #pragma unroll
        for (int q = 0; q < 8; q++) {
            ulonglong2 h = *(const ulonglong2*)&H[(sub*8+q)*HH + k4*4];  // broadcast
            ffma2(acc[0][q], h.x, w0.x); ffma2(acc[0][q], h.y, w0.y);
            ffma2(acc[1][q], h.x, w1.x); ffma2(acc[1][q], h.y, w1.y);
            ffma2(acc[2][q], h.x, w2.x); ffma2(acc[2][q], h.y, w2.y);
            ffma2(acc[3][q], h.x, w3.x); ffma2(acc[3][q], h.y, w3.y);
        }
    }
}

// ---------------- fused 2-layer LSTM ----------------
// block = 128 threads: u = tid&63 (hidden unit), sub = tid>>6, 8 nodes per
// (u,sub) thread, 16 nodes per block, grid = 128.
__global__ void __launch_bounds__(128, 1)
lstm_fused(const float* __restrict__ inp,
           const float* __restrict__ wih0, const float* __restrict__ whh0,
           const float* __restrict__ bih0, const float* __restrict__ bhh0,
           const float* __restrict__ wih1, const float* __restrict__ whh1,
           const float* __restrict__ bih1, const float* __restrict__ bhh1)
{
    extern __shared__ float sm[];
    float4* w0h = (float4*)sm;            // whh0  [k4][g][u]  (64 KB)
    float4* w1i = w0h + 4096;             // wih1
    float4* w1h = w1i + 4096;             // whh1
    float*  xs  = (float*)(w1h + 4096);   // [16][32][5]
    float*  h0b = xs + 16*TT*FIN;         // [16][64]
    float*  h1b = h0b + 16*HH;            // [16][64]

    const int tid = threadIdx.x;
    const int n0  = blockIdx.x * 16;
    const int u = tid & 63, sub = tid >> 6;

    // stage + pack weights
    for (int i = tid; i < 4096; i += 128) {
        int k4 = i >> 8, g = (i >> 6) & 3, uu = i & 63;
        int row = g*64 + uu;
        w0h[i] = ((const float4*)whh0)[row*16 + k4];
        w1i[i] = ((const float4*)wih1)[row*16 + k4];
        w1h[i] = ((const float4*)whh1)[row*16 + k4];
    }
    for (int i = tid; i < 16*TT*FIN; i += 128) xs[i] = inp[n0*TT*FIN + i];
    for (int i = tid; i < 16*HH; i += 128) { h0b[i] = 0.0f; h1b[i] = 0.0f; }

    float wi0[4][FIN];
    float b0[4], b1[4];
    #pragma unroll
    for (int g = 0; g < 4; g++) {
        #pragma unroll
        for (int k = 0; k < FIN; k++) wi0[g][k] = wih0[(g*64+u)*FIN + k];
        b0[g] = bih0[g*64+u] + bhh0[g*64+u];
        b1[g] = bih1[g*64+u] + bhh1[g*64+u];
    }
    float c0[8], c1[8];
    #pragma unroll
    for (int q = 0; q < 8; q++) { c0[q] = 0.0f; c1[q] = 0.0f; }
    __syncthreads();

    for (int t = 0; t < TT; t++) {
        // ---- layer 0 ----
        unsigned long long acc[4][8];
        #pragma unroll
        for (int g = 0; g < 4; g++)
            #pragma unroll
            for (int q = 0; q < 8; q++) acc[g][q] = 0ull;

        gemm64(acc, w0h, h0b, u, sub);

        float hn[8];
        #pragma unroll
        for (int q = 0; q < 8; q++) {
            float xv[FIN];
            #pragma unroll
            for (int k = 0; k < FIN; k++) xv[k] = xs[(sub*8+q)*TT*FIN + t*FIN + k];
            float gt[4];
            #pragma unroll
            for (int g = 0; g < 4; g++) {
                float2 v = unpk(acc[g][q]);
                float a = v.x + v.y + b0[g];
                #pragma unroll
                for (int k = 0; k < FIN; k++) a += wi0[g][k]*xv[k];
                gt[g] = a;
            }
            float gi = fsig(gt[0]), gf = fsig(gt[1]);
            float gg = ftanh(gt[2]), go = fsig(gt[3]);
            c0[q] = gf*c0[q] + gi*gg;
            hn[q] = go*ftanh(c0[q]);
        }
        __syncthreads();
        #pragma unroll
        for (int q = 0; q < 8; q++) h0b[(sub*8+q)*HH + u] = hn[q];
        __syncthreads();

        // ---- layer 1 ----
        #pragma unroll
        for (int g = 0; g < 4; g++)
            #pragma unroll
            for (int q = 0; q < 8; q++) acc[g][q] = 0ull;

        gemm64(acc, w1i, h0b, u, sub);   // input term (x = h0[t])
        gemm64(acc, w1h, h1b, u, sub);   // recurrent term

        #pragma unroll
        for (int q = 0; q < 8; q++) {
            float gt[4];
            #pragma unroll
            for (int g = 0; g < 4; g++) {
                float2 v = unpk(acc[g][q]);
                gt[g] = v.x + v.y + b1[g];
            }
            float gi = fsig(gt[0]), gf = fsig(gt[1]);
            float gg = ftanh(gt[2]), go = fsig(gt[3]);
            c1[q] = gf*c1[q] + gi*gg;
            hn[q] = go*ftanh(c1[q]);
        }
        __syncthreads();
        #pragma unroll
        for (int q = 0; q < 8; q++) h1b[(sub*8+q)*HH + u] = hn[q];
        if (t == TT-1) {
            #pragma unroll
            for (int q = 0; q < 8; q++)
                g_xlast[(n0+sub*8+q)*HH + u] = hn[q];
        }
        __syncthreads();
    }
}

// ---------------- adjacency bitmask ----------------
// adj[n][m] = (rel_mask[n][m]==0) || (n==m). Masked entries are -1e9; fp32
// softmax underflows them to exactly 0, so ws>0 == this mask.
__global__ void adj_kernel(const float* __restrict__ relm)
{
    __shared__ int s[32][33];
    const int tid = threadIdx.x;
    const int m0 = blockIdx.x * 32, n0 = blockIdx.y * 32;
    {
        int nl = tid >> 5, ml = tid & 31;
        float v = relm[(size_t)(n0+nl)*NN + (m0+ml)];
        s[nl][ml] = (v == 0.0f) || ((n0+nl) == (m0+ml));
    }
    __syncthreads();
    {
        int mcol = tid >> 5, nlane = tid & 31;
        unsigned w = __ballot_sync(0xffffffffu, s[nlane][mcol] != 0);
        if (nlane == 0) g_adj[(m0+mcol)*NW + blockIdx.y] = w;
    }
}

// ---------------- GAT1 prep: h1 = x@W1, hs1, hd1 ----------------
// block 256 = 16 nodes x 16 j; grid 128
__global__ void prep1_kernel(const float* __restrict__ W,
                             const float* __restrict__ as,
                             const float* __restrict__ ad)
{
    __shared__ float Ws[HH*GH], xsm[16*HH], ass[GH], ads[GH];
    const int tid = threadIdx.x;
    const int n0 = blockIdx.x * 16;
    for (int i = tid; i < HH*GH; i += 256) Ws[i] = W[i];
    for (int i = tid; i < 16*HH; i += 256) xsm[i] = g_xlast[n0*HH + i];
    if (tid < GH) { ass[tid] = as[tid]; ads[tid] = ad[tid]; }
    __syncthreads();

    const int j = tid & 15, nl = tid >> 4;
    float sj = 0.0f;
    #pragma unroll
    for (int k = 0; k < HH; k++) sj += xsm[nl*HH + k] * Ws[k*GH + j];
    g_h1[(n0+nl)*GH + j] = sj;

    float ps = sj*ass[j], pd = sj*ads[j];
    #pragma unroll
    for (int o = 8; o; o >>= 1) {
        ps += __shfl_xor_sync(0xffffffffu, ps, o);
        pd += __shfl_xor_sync(0xffffffffu, pd, o);
    }
    if (j == 0) { g_hs1[n0+nl] = ps; g_hd1[n0+nl] = pd; }
}

// ---------------- GAT1 aggregate ----------------
__global__ void gat1_agg_kernel(const float* __restrict__ b1)
{
    const int lane = threadIdx.x & 31;
    const int m = blockIdx.x*8 + (threadIdx.x >> 5);
    const float hdm = g_hd1[m];
    const unsigned* row = &g_adj[m*NW];

    float mx = -3.4e38f;
    for (int it = 0; it < NW; it++) {
        unsigned w = row[it];
        if ((w >> lane) & 1u) mx = fmaxf(mx, g_hs1[it*32 + lane]);
    }
    mx = wredmax(mx);
    const float emax = lrelu(mx + hdm);

    float s = 0.f;
    float acc[GH];
    #pragma unroll
    for (int j = 0; j < GH; j++) acc[j] = 0.f;

    for (int it = 0; it < NW; it++) {
        unsigned w = row[it];
        if ((w >> lane) & 1u) {
            int n = it*32 + lane;
            float p = __expf(lrelu(g_hs1[n] + hdm) - emax);
            s += p;
            const float4* hr = (const float4*)&g_h1[n*GH];
            #pragma unroll
            for (int i = 0; i < 4; i++) {
                float4 tv = hr[i];
                acc[4*i]   += p*tv.x; acc[4*i+1] += p*tv.y;
                acc[4*i+2] += p*tv.z; acc[4*i+3] += p*tv.w;
            }
        }
    }
    s = wredsum(s);
    #pragma unroll
    for (int j = 0; j < GH; j++) acc[j] = wredsum(acc[j]);

    if (lane == 0) {
        float inv = 1.0f / s;
        #pragma unroll
        for (int j = 0; j < GH; j++)
            g_out1[m*GH + j] = fmaxf(acc[j]*inv + b1[j], 0.0f);
    }
}

// ---------------- GAT2 prep (folds fc): warp per node, grid 256 ----------------
__global__ void prep2_kernel(const float* __restrict__ W2,
                             const float* __restrict__ as2,
                             const float* __restrict__ ad2,
                             const float* __restrict__ b2,
                             const float* __restrict__ fcw,
                             const float* __restrict__ fcb)
{
    __shared__ float Ws[GH*HH], as_s[HH], ad_s[HH], fc_s[HH], o1s[8*GH];
    const int tid = threadIdx.x;
    const int n0 = blockIdx.x * 8;
    for (int i = tid; i < GH*HH; i += 256) Ws[i] = W2[i];
    for (int i = tid; i < 8*GH; i += 256) o1s[i] = g_out1[n0*GH + i];
    if (tid < HH) { as_s[tid] = as2[tid]; ad_s[tid] = ad2[tid]; fc_s[tid] = fcw[tid]; }
    __syncthreads();

    const int lane = tid & 31, nl = tid >> 5;
    const int n = n0 + nl;
    float hA = 0.f, hB = 0.f;
    #pragma unroll
    for (int k = 0; k < GH; k++) {
        float o = o1s[nl*GH + k];
        hA += o * Ws[k*HH + lane];
        hB += o * Ws[k*HH + lane + 32];
    }
    float hs = hA*as_s[lane] + hB*as_s[lane+32];
    float hd = hA*ad_s[lane] + hB*ad_s[lane+32];
    float hf = hA*fc_s[lane] + hB*fc_s[lane+32];
    hs = wredsum(hs); hd = wredsum(hd); hf = wredsum(hf);
    if (lane == 0) { g_hs2[n] = hs; g_hd2[n] = hd; g_hfc[n] = hf; }

    if (blockIdx.x == 0 && tid == 0) {
        float cb = fcb[0];
        for (int j = 0; j < HH; j++) cb += b2[j]*fcw[j];
        g_cbias = cb;
    }
}

// ---------------- GAT2 aggregate + fc ----------------
__global__ void gat2_agg_kernel(float* __restrict__ out)
{
    const int lane = threadIdx.x & 31;
    const int m = blockIdx.x*8 + (threadIdx.x >> 5);
    const float hdm = g_hd2[m];
    const unsigned* row = &g_adj[m*NW];

    float mx = -3.4e38f;
    for (int it = 0; it < NW; it++) {
        unsigned w = row[it];
        if ((w >> lane) & 1u) mx = fmaxf(mx, g_hs2[it*32 + lane]);
    }
    mx = wredmax(mx);
    const float emax = lrelu(mx + hdm);

    float s = 0.f, a = 0.f;
    for (int it = 0; it < NW; it++) {
        unsigned w = row[it];
        if ((w >> lane) & 1u) {
            int n = it*32 + lane;
            float p = __expf(lrelu(g_hs2[n] + hdm) - emax);
            s += p;
            a += p * g_hfc[n];
        }
    }
    s = wredsum(s);
    a = wredsum(a);
    if (lane == 0) out[m] = lrelu(a/s + g_cbias);
}

// ---------------- launch ----------------
extern "C" void kernel_launch(void* const* d_in, const int* in_sizes, int n_in,
                              void* d_out, int out_size)
{
    const float* inputs = (const float*)d_in[0];
    const float* relm   = (const float*)d_in[2];
    const float* w_ih0  = (const float*)d_in[5];
    const float* w_hh0  = (const float*)d_in[6];
    const float* b_ih0  = (const float*)d_in[7];
    const float* b_hh0  = (const float*)d_in[8];
    const float* w_ih1  = (const float*)d_in[9];
    const float* w_hh1  = (const float*)d_in[10];
    const float* b_ih1  = (const float*)d_in[11];
    const float* b_hh1  = (const float*)d_in[12];
    const float* gat1_W  = (const float*)d_in[13];
    const float* gat1_as = (const float*)d_in[14];
    const float* gat1_ad = (const float*)d_in[15];
    const float* gat1_b  = (const float*)d_in[16];
    const float* gat2_W  = (const float*)d_in[17];
    const float* gat2_as = (const float*)d_in[18];
    const float* gat2_ad = (const float*)d_in[19];
    const float* gat2_b  = (const float*)d_in[20];
    const float* fc_W    = (const float*)d_in[21];
    const float* fc_b    = (const float*)d_in[22];
    float* out = (float*)d_out;

    const int smemL = (3*4096*4 + 16*TT*FIN + 2*16*HH) * 4;  // 215040 B
    static int configured = 0;
    cudaFuncSetAttribute(lstm_fused, cudaFuncAttributeMaxDynamicSharedMemorySize, smemL);
    (void)configured;

    lstm_fused<<<NN/16, 128, smemL>>>(inputs, w_ih0, w_hh0, b_ih0, b_hh0,
                                      w_ih1, w_hh1, b_ih1, b_hh1);
    adj_kernel<<<dim3(NN/32, NN/32), 1024>>>(relm);
    prep1_kernel<<<NN/16, 256>>>(gat1_W, gat1_as, gat1_ad);
    gat1_agg_kernel<<<NN/8, 256>>>(gat1_b);
    prep2_kernel<<<NN/8, 256>>>(gat2_W, gat2_as, gat2_ad, gat2_b, fc_W, fc_b);
    gat2_agg_kernel<<<NN/8, 256>>>(out);
}

// round 6
// speedup vs baseline: 1.1715x; 1.1021x over previous
#include <cuda_runtime.h>

#define NN 2048
#define TT 32
#define FIN 5
#define HH 64
#define GH 16
#define NW (NN/32)

// ---------------- scratch ----------------
__device__ float    g_xlast[NN*HH];
__device__ unsigned g_adj[NN*NW];
__device__ float    g_h1[NN*GH];
__device__ float    g_hs1[NN];
__device__ float    g_hd1[NN];
__device__ float    g_out1[NN*GH];
__device__ float    g_hs2[NN];
__device__ float    g_hd2[NN];
__device__ float    g_hfc[NN];
__device__ float    g_cbias;

__device__ __forceinline__ float fsig(float x)  { return 1.0f/(1.0f+__expf(-x)); }
__device__ __forceinline__ float ftanh(float x) { return 1.0f - 2.0f/(__expf(2.0f*x)+1.0f); }
__device__ __forceinline__ float lrelu(float x) { return x > 0.0f ? x : 0.2f*x; }

__device__ __forceinline__ float wredmax(float v){
    #pragma unroll
    for (int o = 16; o; o >>= 1) v = fmaxf(v, __shfl_xor_sync(0xffffffffu, v, o));
    return v;
}
__device__ __forceinline__ float wredsum(float v){
    #pragma unroll
    for (int o = 16; o; o >>= 1) v += __shfl_xor_sync(0xffffffffu, v, o);
    return v;
}

// packed fp32x2 FMA: d.lo += a.lo*b.lo ; d.hi += a.hi*b.hi
__device__ __forceinline__ void ffma2(unsigned long long &d,
                                      unsigned long long a,
                                      unsigned long long b){
    asm("fma.rn.f32x2 %0, %1, %2, %0;" : "+l"(d) : "l"(a), "l"(b));
}
__device__ __forceinline__ float2 unpk(unsigned long long v){
    float2 r; asm("mov.b64 {%0, %1}, %2;" : "=f"(r.x), "=f"(r.y) : "l"(v));
    return r;
}

// 64-k GEMM accumulate for 2 gates x 8 nodes.
// W packed [k4][gate(4)][u(64)] as float4 over k; thread uses gates gp*2, gp*2+1.
__device__ __forceinline__ void gemm64b(unsigned long long acc0[8],
                                        unsigned long long acc1[8],
                                        const float4* __restrict__ W,
                                        const float*  __restrict__ H,
                                        int u, int gp, int sub)
{
    const ulonglong2* Wu = (const ulonglong2*)W + gp*128 + u;
    const float* Hb = H + sub*8*HH;
    #pragma unroll 4
    for (int k4 = 0; k4 < 16; k4++) {
        ulonglong2 wa = Wu[k4*256];
        ulonglong2 wb = Wu[k4*256 + 64];
        #pragma unroll
        for (int q = 0; q < 8; q++) {
            ulonglong2 h = *(const ulonglong2*)&Hb[q*HH + k4*4];  // warp broadcast
            ffma2(acc0[q], h.x, wa.x); ffma2(acc0[q], h.y, wa.y);
            ffma2(acc1[q], h.x, wb.x); ffma2(acc1[q], h.y, wb.y);
        }
    }
}

// ---------------- fused 2-layer LSTM ----------------
// 256 threads: u = tid&63 (unit), gp = (tid>>6)&1 (gates {i,f} or {g,o}),
// sub = tid>>7; 8 nodes per thread, 16 nodes/block, grid 128.
// 2 warps per SMSP; gp halves exchanged through smem pbuf.
__global__ void __launch_bounds__(256, 1)
lstm_fused(const float* __restrict__ inp,
           const float* __restrict__ wih0, const float* __restrict__ whh0,
           const float* __restrict__ bih0, const float* __restrict__ bhh0,
           const float* __restrict__ wih1, const float* __restrict__ whh1,
           const float* __restrict__ bih1, const float* __restrict__ bhh1)
{
    extern __shared__ float sm[];
    float4* w0h = (float4*)sm;            // whh0 [k4][g][u]  64 KB
    float4* w1i = w0h + 4096;             // wih1
    float4* w1h = w1i + 4096;             // whh1
    float*  xs  = (float*)(w1h + 4096);   // [16][32][5]
    float*  h0b = xs + 16*TT*FIN;         // [16][64]
    float*  h1b = h0b + 16*HH;            // [16][64]
    float2* pbuf= (float2*)(h1b + 16*HH); // [16][64] (pi,pf) exchange

    const int tid = threadIdx.x;
    const int n0  = blockIdx.x * 16;
    const int u = tid & 63, gp = (tid >> 6) & 1, sub = tid >> 7;

    for (int i = tid; i < 4096; i += 256) {
        int k4 = i >> 8, g = (i >> 6) & 3, uu = i & 63;
        int row = g*64 + uu;
        w0h[i] = ((const float4*)whh0)[row*16 + k4];
        w1i[i] = ((const float4*)wih1)[row*16 + k4];
        w1h[i] = ((const float4*)whh1)[row*16 + k4];
    }
    for (int i = tid; i < 16*TT*FIN; i += 256) xs[i] = inp[n0*TT*FIN + i];
    for (int i = tid; i < 16*HH; i += 256) { h0b[i] = 0.0f; h1b[i] = 0.0f; }

    // per-thread layer0 input weights + biases for this thread's 2 gates
    float wi0[2][FIN], b0[2], b1[2];
    #pragma unroll
    for (int g = 0; g < 2; g++) {
        int row = (gp*2 + g)*64 + u;
        #pragma unroll
        for (int k = 0; k < FIN; k++) wi0[g][k] = wih0[row*FIN + k];
        b0[g] = bih0[row] + bhh0[row];
        b1[g] = bih1[row] + bhh1[row];
    }
    float c0[8], c1[8];
    #pragma unroll
    for (int q = 0; q < 8; q++) { c0[q] = 0.0f; c1[q] = 0.0f; }
    __syncthreads();

    unsigned long long a0[8], a1[8];
    float pa[8], pb[8];

    for (int t = 0; t < TT; t++) {
        // ======== layer 0 ========
        #pragma unroll
        for (int q = 0; q < 8; q++) { a0[q] = 0ull; a1[q] = 0ull; }
        gemm64b(a0, a1, w0h, h0b, u, gp, sub);

        #pragma unroll
        for (int q = 0; q < 8; q++) {
            float2 v0 = unpk(a0[q]), v1 = unpk(a1[q]);
            float g0 = v0.x + v0.y + b0[0];
            float g1 = v1.x + v1.y + b0[1];
            const float* xv = &xs[(sub*8+q)*TT*FIN + t*FIN];
            #pragma unroll
            for (int k = 0; k < FIN; k++) {
                float x = xv[k];
                g0 += wi0[0][k]*x; g1 += wi0[1][k]*x;
            }
            if (gp == 0) { pa[q] = fsig(g0);  pb[q] = fsig(g1); }   // i, f
            else         { pa[q] = ftanh(g0); pb[q] = fsig(g1); }   // g, o
        }
        if (gp == 0) {
            #pragma unroll
            for (int q = 0; q < 8; q++) pbuf[(sub*8+q)*64 + u] = make_float2(pa[q], pb[q]);
        }
        __syncthreads();
        if (gp == 1) {
            #pragma unroll
            for (int q = 0; q < 8; q++) {
                float2 sif = pbuf[(sub*8+q)*64 + u];
                c0[q] = sif.y*c0[q] + sif.x*pa[q];
                h0b[(sub*8+q)*HH + u] = pb[q]*ftanh(c0[q]);
            }
        }
        __syncthreads();

        // ======== layer 1 ========
        #pragma unroll
        for (int q = 0; q < 8; q++) { a0[q] = 0ull; a1[q] = 0ull; }
        gemm64b(a0, a1, w1i, h0b, u, gp, sub);   // input term (x = h0[t])
        gemm64b(a0, a1, w1h, h1b, u, gp, sub);   // recurrent term

        #pragma unroll
        for (int q = 0; q < 8; q++) {
            float2 v0 = unpk(a0[q]), v1 = unpk(a1[q]);
            float g0 = v0.x + v0.y + b1[0];
            float g1 = v1.x + v1.y + b1[1];
            if (gp == 0) { pa[q] = fsig(g0);  pb[q] = fsig(g1); }
            else         { pa[q] = ftanh(g0); pb[q] = fsig(g1); }
        }
        if (gp == 0) {
            #pragma unroll
            for (int q = 0; q < 8; q++) pbuf[(sub*8+q)*64 + u] = make_float2(pa[q], pb[q]);
        }
        __syncthreads();
        if (gp == 1) {
            #pragma unroll
            for (int q = 0; q < 8; q++) {
                float2 sif = pbuf[(sub*8+q)*64 + u];
                c1[q] = sif.y*c1[q] + sif.x*pa[q];
                float h = pb[q]*ftanh(c1[q]);
                h1b[(sub*8+q)*HH + u] = h;
                if (t == TT-1) g_xlast[(n0+sub*8+q)*HH + u] = h;
            }
        }
        __syncthreads();
    }
}

// ---------------- adjacency bitmask ----------------
// adj[n][m] = (rel_mask[n][m]==0) || (n==m); fp32 softmax zeroes -1e9 entries.
__global__ void adj_kernel(const float* __restrict__ relm)
{
    __shared__ int s[32][33];
    const int tid = threadIdx.x;
    const int m0 = blockIdx.x * 32, n0 = blockIdx.y * 32;
    {
        int nl = tid >> 5, ml = tid & 31;
        float v = relm[(size_t)(n0+nl)*NN + (m0+ml)];
        s[nl][ml] = (v == 0.0f) || ((n0+nl) == (m0+ml));
    }
    __syncthreads();
    {
        int mcol = tid >> 5, nlane = tid & 31;
        unsigned w = __ballot_sync(0xffffffffu, s[nlane][mcol] != 0);
        if (nlane == 0) g_adj[(m0+mcol)*NW + blockIdx.y] = w;
    }
}

// ---------------- GAT1 prep: h1 = x@W1, hs1, hd1 ----------------
__global__ void prep1_kernel(const float* __restrict__ W,
                             const float* __restrict__ as,
                             const float* __restrict__ ad)
{
    __shared__ float Ws[HH*GH], xsm[16*HH], ass[GH], ads[GH];
    const int tid = threadIdx.x;
    const int n0 = blockIdx.x * 16;
    for (int i = tid; i < HH*GH; i += 256) Ws[i] = W[i];
    for (int i = tid; i < 16*HH; i += 256) xsm[i] = g_xlast[n0*HH + i];
    if (tid < GH) { ass[tid] = as[tid]; ads[tid] = ad[tid]; }
    __syncthreads();

    const int j = tid & 15, nl = tid >> 4;
    float sj = 0.0f;
    #pragma unroll
    for (int k = 0; k < HH; k++) sj += xsm[nl*HH + k] * Ws[k*GH + j];
    g_h1[(n0+nl)*GH + j] = sj;

    float ps = sj*ass[j], pd = sj*ads[j];
    #pragma unroll
    for (int o = 8; o; o >>= 1) {
        ps += __shfl_xor_sync(0xffffffffu, ps, o);
        pd += __shfl_xor_sync(0xffffffffu, pd, o);
    }
    if (j == 0) { g_hs1[n0+nl] = ps; g_hd1[n0+nl] = pd; }
}

// ---------------- GAT1 aggregate (no max pass; e is O(1) so exp is safe) ----------------
__global__ void gat1_agg_kernel(const float* __restrict__ b1)
{
    __shared__ float hs_s[NN];
    const int tid = threadIdx.x, lane = tid & 31;
    for (int i = tid; i < NN; i += 256) hs_s[i] = g_hs1[i];
    __syncthreads();

    const int m = blockIdx.x*8 + (tid >> 5);
    const float hdm = g_hd1[m];
    const unsigned* row = &g_adj[m*NW];

    float s = 0.f;
    float acc[GH];
    #pragma unroll
    for (int j = 0; j < GH; j++) acc[j] = 0.f;

    for (int it = 0; it < NW; it++) {
        unsigned w = row[it];
        if (w == 0u) continue;
        if ((w >> lane) & 1u) {
            int n = it*32 + lane;
            float p = __expf(lrelu(hs_s[n] + hdm));
            s += p;
            const float4* hr = (const float4*)&g_h1[n*GH];
            #pragma unroll
            for (int i = 0; i < 4; i++) {
                float4 tv = hr[i];
                acc[4*i]   += p*tv.x; acc[4*i+1] += p*tv.y;
                acc[4*i+2] += p*tv.z; acc[4*i+3] += p*tv.w;
            }
        }
    }
    s = wredsum(s);
    #pragma unroll
    for (int j = 0; j < GH; j++) acc[j] = wredsum(acc[j]);

    if (lane == 0) {
        float inv = 1.0f / s;
        #pragma unroll
        for (int j = 0; j < GH; j++)
            g_out1[m*GH + j] = fmaxf(acc[j]*inv + b1[j], 0.0f);
    }
}

// ---------------- GAT2 prep (folds fc) ----------------
__global__ void prep2_kernel(const float* __restrict__ W2,
                             const float* __restrict__ as2,
                             const float* __restrict__ ad2,
                             const float* __restrict__ b2,
                             const float* __restrict__ fcw,
                             const float* __restrict__ fcb)
{
    __shared__ float Ws[GH*HH], as_s[HH], ad_s[HH], fc_s[HH], o1s[8*GH];
    const int tid = threadIdx.x;
    const int n0 = blockIdx.x * 8;
    for (int i = tid; i < GH*HH; i += 256) Ws[i] = W2[i];
    for (int i = tid; i < 8*GH; i += 256) o1s[i] = g_out1[n0*GH + i];
    if (tid < HH) { as_s[tid] = as2[tid]; ad_s[tid] = ad2[tid]; fc_s[tid] = fcw[tid]; }
    __syncthreads();

    const int lane = tid & 31, nl = tid >> 5;
    const int n = n0 + nl;
    float hA = 0.f, hB = 0.f;
    #pragma unroll
    for (int k = 0; k < GH; k++) {
        float o = o1s[nl*GH + k];
        hA += o * Ws[k*HH + lane];
        hB += o * Ws[k*HH + lane + 32];
    }
    float hs = hA*as_s[lane] + hB*as_s[lane+32];
    float hd = hA*ad_s[lane] + hB*ad_s[lane+32];
    float hf = hA*fc_s[lane] + hB*fc_s[lane+32];
    hs = wredsum(hs); hd = wredsum(hd); hf = wredsum(hf);
    if (lane == 0) { g_hs2[n] = hs; g_hd2[n] = hd; g_hfc[n] = hf; }

    if (blockIdx.x == 0 && tid == 0) {
        float cb = fcb[0];
        for (int j = 0; j < HH; j++) cb += b2[j]*fcw[j];
        g_cbias = cb;
    }
}

// ---------------- GAT2 aggregate + fc (no max pass) ----------------
__global__ void gat2_agg_kernel(float* __restrict__ out)
{
    __shared__ float hs_s[NN], hf_s[NN];
    const int tid = threadIdx.x, lane = tid & 31;
    for (int i = tid; i < NN; i += 256) { hs_s[i] = g_hs2[i]; hf_s[i] = g_hfc[i]; }
    __syncthreads();

    const int m = blockIdx.x*8 + (tid >> 5);
    const float hdm = g_hd2[m];
    const unsigned* row = &g_adj[m*NW];

    float s = 0.f, a = 0.f;
    for (int it = 0; it < NW; it++) {
        unsigned w = row[it];
        if (w == 0u) continue;
        if ((w >> lane) & 1u) {
            int n = it*32 + lane;
            float p = __expf(lrelu(hs_s[n] + hdm));
            s += p;
            a += p * hf_s[n];
        }
    }
    s = wredsum(s);
    a = wredsum(a);
    if (lane == 0) out[m] = lrelu(a/s + g_cbias);
}

// ---------------- launch ----------------
extern "C" void kernel_launch(void* const* d_in, const int* in_sizes, int n_in,
                              void* d_out, int out_size)
{
    const float* inputs = (const float*)d_in[0];
    const float* relm   = (const float*)d_in[2];
    const float* w_ih0  = (const float*)d_in[5];
    const float* w_hh0  = (const float*)d_in[6];
    const float* b_ih0  = (const float*)d_in[7];
    const float* b_hh0  = (const float*)d_in[8];
    const float* w_ih1  = (const float*)d_in[9];
    const float* w_hh1  = (const float*)d_in[10];
    const float* b_ih1  = (const float*)d_in[11];
    const float* b_hh1  = (const float*)d_in[12];
    const float* gat1_W  = (const float*)d_in[13];
    const float* gat1_as = (const float*)d_in[14];
    const float* gat1_ad = (const float*)d_in[15];
    const float* gat1_b  = (const float*)d_in[16];
    const float* gat2_W  = (const float*)d_in[17];
    const float* gat2_as = (const float*)d_in[18];
    const float* gat2_ad = (const float*)d_in[19];
    const float* gat2_b  = (const float*)d_in[20];
    const float* fc_W    = (const float*)d_in[21];
    const float* fc_b    = (const float*)d_in[22];
    float* out = (float*)d_out;

    // weights 192KB + xs 10KB + h buffers 8KB + pbuf 8KB = 218KB
    const int smemL = 3*4096*16 + (16*TT*FIN + 2*16*HH)*4 + 16*HH*8;
    cudaFuncSetAttribute(lstm_fused, cudaFuncAttributeMaxDynamicSharedMemorySize, smemL);

    lstm_fused<<<NN/16, 256, smemL>>>(inputs, w_ih0, w_hh0, b_ih0, b_hh0,
                                      w_ih1, w_hh1, b_ih1, b_hh1);
    adj_kernel<<<dim3(NN/32, NN/32), 1024>>>(relm);
    prep1_kernel<<<NN/16, 256>>>(gat1_W, gat1_as, gat1_ad);
    gat1_agg_kernel<<<NN/8, 256>>>(gat1_b);
    prep2_kernel<<<NN/8, 256>>>(gat2_W, gat2_as, gat2_ad, gat2_b, fc_W, fc_b);
    gat2_agg_kernel<<<NN/8, 256>>>(out);
}

// round 9
// speedup vs baseline: 1.1954x; 1.0204x over previous
#include <cuda_runtime.h>

#define NN 2048
#define TT 32
#define FIN 5
#define HH 64
#define GH 16
#define NW (NN/32)

// ---------------- scratch ----------------
__device__ float    g_xlast[NN*HH];
__device__ unsigned g_adj[NN*NW];
__device__ float    g_h1[NN*GH];
__device__ float    g_hs1[NN];
__device__ float    g_hd1[NN];
__device__ float    g_out1[NN*GH];
__device__ float    g_hs2[NN];
__device__ float    g_hd2[NN];
__device__ float    g_hfc[NN];
__device__ float    g_cbias;

__device__ __forceinline__ float fsig(float x)  { return 1.0f/(1.0f+__expf(-x)); }
__device__ __forceinline__ float ftanh(float x) { return 1.0f - 2.0f/(__expf(2.0f*x)+1.0f); }
__device__ __forceinline__ float lrelu(float x) { return x > 0.0f ? x : 0.2f*x; }

__device__ __forceinline__ float wredsum(float v){
    #pragma unroll
    for (int o = 16; o; o >>= 1) v += __shfl_xor_sync(0xffffffffu, v, o);
    return v;
}

// packed fp32x2 FMA: d.lo += a.lo*b.lo ; d.hi += a.hi*b.hi
__device__ __forceinline__ void ffma2(unsigned long long &d,
                                      unsigned long long a,
                                      unsigned long long b){
    asm("fma.rn.f32x2 %0, %1, %2, %0;" : "+l"(d) : "l"(a), "l"(b));
}
__device__ __forceinline__ float2 unpk(unsigned long long v){
    float2 r; asm("mov.b64 {%0, %1}, %2;" : "=f"(r.x), "=f"(r.y) : "l"(v));
    return r;
}

// 64-k GEMM accumulate for 2 gates x 8 nodes.
// W packed [k4][gate(4)][u(64)] as float4 over k; thread uses gates gp*2, gp*2+1.
__device__ __forceinline__ void gemm64b(unsigned long long acc0[8],
                                        unsigned long long acc1[8],
                                        const float4* __restrict__ W,
                                        const float*  __restrict__ H,
                                        int u, int gp, int sub)
{
    const ulonglong2* Wu = (const ulonglong2*)W + gp*128 + u;
    const float* Hb = H + sub*8*HH;
    #pragma unroll 4
    for (int k4 = 0; k4 < 16; k4++) {
        ulonglong2 wa = Wu[k4*256];
        ulonglong2 wb = Wu[k4*256 + 64];
        #pragma unroll
        for (int q = 0; q < 8; q++) {
            ulonglong2 h = *(const ulonglong2*)&Hb[q*HH + k4*4];  // warp broadcast
            ffma2(acc0[q], h.x, wa.x); ffma2(acc0[q], h.y, wa.y);
            ffma2(acc1[q], h.x, wb.x); ffma2(acc1[q], h.y, wb.y);
        }
    }
}

// ---------------- fused 2-layer LSTM ----------------
// 256 threads: u = tid&63, sub = (tid>>6)&1 (node group of 8),
// gp = (tid>>7)&1 (gates {i,f} or {g,o}).
// Warps 0-3 = gp0, warps 4-7 = gp1  -> every SMSP holds one gp0 + one gp1
// warp (balanced MUFU + balanced barrier arrival).
__global__ void __launch_bounds__(256, 1)
lstm_fused(const float* __restrict__ inp,
           const float* __restrict__ wih0, const float* __restrict__ whh0,
           const float* __restrict__ bih0, const float* __restrict__ bhh0,
           const float* __restrict__ wih1, const float* __restrict__ whh1,
           const float* __restrict__ bih1, const float* __restrict__ bhh1)
{
    extern __shared__ float sm[];
    float4* w0h = (float4*)sm;            // whh0 [k4][g][u]  64 KB
    float4* w1i = w0h + 4096;             // wih1
    float4* w1h = w1i + 4096;             // whh1
    float4* xs4 = (float4*)(w1h + 4096);  // [16][32] x k0..3   8 KB
    float*  xs1 = (float*)(xs4 + 16*TT);  // [16][32] x k4      2 KB
    float*  h0b = xs1 + 16*TT;            // [16][64]
    float*  h1b = h0b + 16*HH;            // [16][64]
    float2* pbuf= (float2*)(h1b + 16*HH); // [16][64] (pi,pf) exchange

    const int tid = threadIdx.x;
    const int n0  = blockIdx.x * 16;
    const int u = tid & 63, sub = (tid >> 6) & 1, gp = (tid >> 7) & 1;

    for (int i = tid; i < 4096; i += 256) {
        int k4 = i >> 8, g = (i >> 6) & 3, uu = i & 63;
        int row = g*64 + uu;
        w0h[i] = ((const float4*)whh0)[row*16 + k4];
        w1i[i] = ((const float4*)wih1)[row*16 + k4];
        w1h[i] = ((const float4*)whh1)[row*16 + k4];
    }
    // stage inputs split into aligned float4 (k0..3) + float (k4)
    for (int i = tid; i < 16*TT; i += 256) {
        int nl = i / TT, t = i % TT;
        const float* src = &inp[(n0+nl)*TT*FIN + t*FIN];
        xs4[nl*TT + t] = make_float4(src[0], src[1], src[2], src[3]);
        xs1[nl*TT + t] = src[4];
    }
    for (int i = tid; i < 16*HH; i += 256) { h0b[i] = 0.0f; h1b[i] = 0.0f; }

    // per-thread layer0 input weights + biases for this thread's 2 gates
    float wi0[2][FIN], b0[2], b1[2];
    #pragma unroll
    for (int g = 0; g < 2; g++) {
        int row = (gp*2 + g)*64 + u;
        #pragma unroll
        for (int k = 0; k < FIN; k++) wi0[g][k] = wih0[row*FIN + k];
        b0[g] = bih0[row] + bhh0[row];
        b1[g] = bih1[row] + bhh1[row];
    }
    float c0[8], c1[8];
    #pragma unroll
    for (int q = 0; q < 8; q++) { c0[q] = 0.0f; c1[q] = 0.0f; }
    __syncthreads();

    unsigned long long a0[8], a1[8];
    float pa[8], pb[8];

    for (int t = 0; t < TT; t++) {
        // ======== layer 0 ========
        #pragma unroll
        for (int q = 0; q < 8; q++) { a0[q] = 0ull; a1[q] = 0ull; }
        gemm64b(a0, a1, w0h, h0b, u, gp, sub);

        #pragma unroll
        for (int q = 0; q < 8; q++) {
            float2 v0 = unpk(a0[q]), v1 = unpk(a1[q]);
            float g0 = v0.x + v0.y + b0[0];
            float g1 = v1.x + v1.y + b0[1];
            float4 x4 = xs4[(sub*8+q)*TT + t];
            float  x1 = xs1[(sub*8+q)*TT + t];
            g0 += wi0[0][0]*x4.x + wi0[0][1]*x4.y + wi0[0][2]*x4.z
                + wi0[0][3]*x4.w + wi0[0][4]*x1;
            g1 += wi0[1][0]*x4.x + wi0[1][1]*x4.y + wi0[1][2]*x4.z
                + wi0[1][3]*x4.w + wi0[1][4]*x1;
            if (gp == 0) { pa[q] = fsig(g0);  pb[q] = fsig(g1); }   // i, f
            else         { pa[q] = ftanh(g0); pb[q] = fsig(g1); }   // g, o
        }
        if (gp == 0) {
            #pragma unroll
            for (int q = 0; q < 8; q++) pbuf[(sub*8+q)*64 + u] = make_float2(pa[q], pb[q]);
        }
        __syncthreads();
        if (gp == 1) {
            #pragma unroll
            for (int q = 0; q < 8; q++) {
                float2 sif = pbuf[(sub*8+q)*64 + u];
                c0[q] = sif.y*c0[q] + sif.x*pa[q];
                h0b[(sub*8+q)*HH + u] = pb[q]*ftanh(c0[q]);
            }
        }
        __syncthreads();

        // ======== layer 1 ========
        #pragma unroll
        for (int q = 0; q < 8; q++) { a0[q] = 0ull; a1[q] = 0ull; }
        gemm64b(a0, a1, w1i, h0b, u, gp, sub);   // input term (x = h0[t])
        gemm64b(a0, a1, w1h, h1b, u, gp, sub);   // recurrent term

        #pragma unroll
        for (int q = 0; q < 8; q++) {
            float2 v0 = unpk(a0[q]), v1 = unpk(a1[q]);
            float g0 = v0.x + v0.y + b1[0];
            float g1 = v1.x + v1.y + b1[1];
            if (gp == 0) { pa[q] = fsig(g0);  pb[q] = fsig(g1); }
            else         { pa[q] = ftanh(g0); pb[q] = fsig(g1); }
        }
        if (gp == 0) {
            #pragma unroll
            for (int q = 0; q < 8; q++) pbuf[(sub*8+q)*64 + u] = make_float2(pa[q], pb[q]);
        }
        __syncthreads();
        if (gp == 1) {
            #pragma unroll
            for (int q = 0; q < 8; q++) {
                float2 sif = pbuf[(sub*8+q)*64 + u];
                c1[q] = sif.y*c1[q] + sif.x*pa[q];
                float h = pb[q]*ftanh(c1[q]);
                h1b[(sub*8+q)*HH + u] = h;
                if (t == TT-1) g_xlast[(n0+sub*8+q)*HH + u] = h;
            }
        }
        __syncthreads();
    }
}

// ---------------- adjacency bitmask ----------------
// adj[n][m] = (rel_mask[n][m]==0) || (n==m); fp32 softmax zeroes -1e9 entries.
__global__ void adj_kernel(const float* __restrict__ relm)
{
    __shared__ int s[32][33];
    const int tid = threadIdx.x;
    const int m0 = blockIdx.x * 32, n0 = blockIdx.y * 32;
    {
        int nl = tid >> 5, ml = tid & 31;
        float v = relm[(size_t)(n0+nl)*NN + (m0+ml)];
        s[nl][ml] = (v == 0.0f) || ((n0+nl) == (m0+ml));
    }
    __syncthreads();
    {
        int mcol = tid >> 5, nlane = tid & 31;
        unsigned w = __ballot_sync(0xffffffffu, s[nlane][mcol] != 0);
        if (nlane == 0) g_adj[(m0+mcol)*NW + blockIdx.y] = w;
    }
}

// ---------------- GAT1 prep: h1 = x@W1, hs1, hd1 ----------------
__global__ void prep1_kernel(const float* __restrict__ W,
                             const float* __restrict__ as,
                             const float* __restrict__ ad)
{
    __shared__ float Ws[HH*GH], xsm[16*HH], ass[GH], ads[GH];
    const int tid = threadIdx.x;
    const int n0 = blockIdx.x * 16;
    for (int i = tid; i < HH*GH; i += 256) Ws[i] = W[i];
    for (int i = tid; i < 16*HH; i += 256) xsm[i] = g_xlast[n0*HH + i];
    if (tid < GH) { ass[tid] = as[tid]; ads[tid] = ad[tid]; }
    __syncthreads();

    const int j = tid & 15, nl = tid >> 4;
    float sj = 0.0f;
    #pragma unroll
    for (int k = 0; k < HH; k++) sj += xsm[nl*HH + k] * Ws[k*GH + j];
    g_h1[(n0+nl)*GH + j] = sj;

    float ps = sj*ass[j], pd = sj*ads[j];
    #pragma unroll
    for (int o = 8; o; o >>= 1) {
        ps += __shfl_xor_sync(0xffffffffu, ps, o);
        pd += __shfl_xor_sync(0xffffffffu, pd, o);
    }
    if (j == 0) { g_hs1[n0+nl] = ps; g_hd1[n0+nl] = pd; }
}

// ---------------- GAT1 aggregate: compact edges then dense loop ----------------
__global__ void gat1_agg_kernel(const float* __restrict__ b1)
{
    __shared__ float hs_s[NN];
    __shared__ unsigned short lst[8][256];
    const int tid = threadIdx.x, lane = tid & 31, wi = tid >> 5;
    for (int i = tid; i < NN; i += 256) hs_s[i] = g_hs1[i];
    __syncthreads();

    const int m = blockIdx.x*8 + wi;
    const unsigned* row = &g_adj[m*NW];
    const unsigned below = (lane == 31) ? 0x7fffffffu : ((1u << lane) - 1u);

    int cnt = 0;
    for (int it = 0; it < NW; it++) {
        unsigned w = row[it];                 // broadcast load; w IS the ballot
        if (w == 0u) continue;
        if ((w >> lane) & 1u)
            lst[wi][cnt + __popc(w & below)] = (unsigned short)(it*32 + lane);
        cnt += __popc(w);
    }

    const float hdm = g_hd1[m];
    float s = 0.f;
    float acc[GH];
    #pragma unroll
    for (int j = 0; j < GH; j++) acc[j] = 0.f;

    for (int e = lane; e < cnt; e += 32) {
        int n = lst[wi][e];
        float p = __expf(lrelu(hs_s[n] + hdm));
        s += p;
        const float4* hr = (const float4*)&g_h1[n*GH];
        #pragma unroll
        for (int i = 0; i < 4; i++) {
            float4 tv = hr[i];
            acc[4*i]   += p*tv.x; acc[4*i+1] += p*tv.y;
            acc[4*i+2] += p*tv.z; acc[4*i+3] += p*tv.w;
        }
    }
    s = wredsum(s);
    #pragma unroll
    for (int j = 0; j < GH; j++) acc[j] = wredsum(acc[j]);

    if (lane == 0) {
        float inv = 1.0f / s;
        #pragma unroll
        for (int j = 0; j < GH; j++)
            g_out1[m*GH + j] = fmaxf(acc[j]*inv + b1[j], 0.0f);
    }
}

// ---------------- GAT2 prep (folds fc) ----------------
__global__ void prep2_kernel(const float* __restrict__ W2,
                             const float* __restrict__ as2,
                             const float* __restrict__ ad2,
                             const float* __restrict__ b2,
                             const float* __restrict__ fcw,
                             const float* __restrict__ fcb)
{
    __shared__ float Ws[GH*HH], as_s[HH], ad_s[HH], fc_s[HH], o1s[8*GH];
    const int tid = threadIdx.x;
    const int n0 = blockIdx.x * 8;
    for (int i = tid; i < GH*HH; i += 256) Ws[i] = W2[i];
    for (int i = tid; i < 8*GH; i += 256) o1s[i] = g_out1[n0*GH + i];
    if (tid < HH) { as_s[tid] = as2[tid]; ad_s[tid] = ad2[tid]; fc_s[tid] = fcw[tid]; }
    __syncthreads();

    const int lane = tid & 31, nl = tid >> 5;
    const int n = n0 + nl;
    float hA = 0.f, hB = 0.f;
    #pragma unroll
    for (int k = 0; k < GH; k++) {
        float o = o1s[nl*GH + k];
        hA += o * Ws[k*HH + lane];
        hB += o * Ws[k*HH + lane + 32];
    }
    float hs = hA*as_s[lane] + hB*as_s[lane+32];
    float hd = hA*ad_s[lane] + hB*ad_s[lane+32];
    float hf = hA*fc_s[lane] + hB*fc_s[lane+32];
    hs = wredsum(hs); hd = wredsum(hd); hf = wredsum(hf);
    if (lane == 0) { g_hs2[n] = hs; g_hd2[n] = hd; g_hfc[n] = hf; }

    if (blockIdx.x == 0 && tid == 0) {
        float cb = fcb[0];
        for (int j = 0; j < HH; j++) cb += b2[j]*fcw[j];
        g_cbias = cb;
    }
}

// ---------------- GAT2 aggregate + fc: compact then dense ----------------
__global__ void gat2_agg_kernel(float* __restrict__ out)
{
    __shared__ float hs_s[NN], hf_s[NN];
    __shared__ unsigned short lst[8][256];
    const int tid = threadIdx.x, lane = tid & 31, wi = tid >> 5;
    for (int i = tid; i < NN; i += 256) { hs_s[i] = g_hs2[i]; hf_s[i] = g_hfc[i]; }
    __syncthreads();

    const int m = blockIdx.x*8 + wi;
    const unsigned* row = &g_adj[m*NW];
    const unsigned below = (lane == 31) ? 0x7fffffffu : ((1u << lane) - 1u);

    int cnt = 0;
    for (int it = 0; it < NW; it++) {
        unsigned w = row[it];
        if (w == 0u) continue;
        if ((w >> lane) & 1u)
            lst[wi][cnt + __popc(w & below)] = (unsigned short)(it*32 + lane);
        cnt += __popc(w);
    }

    const float hdm = g_hd2[m];
    float s = 0.f, a = 0.f;
    for (int e = lane; e < cnt; e += 32) {
        int n = lst[wi][e];
        float p = __expf(lrelu(hs_s[n] + hdm));
        s += p;
        a += p * hf_s[n];
    }
    s = wredsum(s);
    a = wredsum(a);
    if (lane == 0) out[m] = lrelu(a/s + g_cbias);
}

// ---------------- launch ----------------
extern "C" void kernel_launch(void* const* d_in, const int* in_sizes, int n_in,
                              void* d_out, int out_size)
{
    const float* inputs = (const float*)d_in[0];
    const float* relm   = (const float*)d_in[2];
    const float* w_ih0  = (const float*)d_in[5];
    const float* w_hh0  = (const float*)d_in[6];
    const float* b_ih0  = (const float*)d_in[7];
    const float* b_hh0  = (const float*)d_in[8];
    const float* w_ih1  = (const float*)d_in[9];
    const float* w_hh1  = (const float*)d_in[10];
    const float* b_ih1  = (const float*)d_in[11];
    const float* b_hh1  = (const float*)d_in[12];
    const float* gat1_W  = (const float*)d_in[13];
    const float* gat1_as = (const float*)d_in[14];
    const float* gat1_ad = (const float*)d_in[15];
    const float* gat1_b  = (const float*)d_in[16];
    const float* gat2_W  = (const float*)d_in[17];
    const float* gat2_as = (const float*)d_in[18];
    const float* gat2_ad = (const float*)d_in[19];
    const float* gat2_b  = (const float*)d_in[20];
    const float* fc_W    = (const float*)d_in[21];
    const float* fc_b    = (const float*)d_in[22];
    float* out = (float*)d_out;

    // weights 192KB + xs4 8KB + xs1 2KB + h bufs 8KB + pbuf 8KB = 218KB
    const int smemL = 3*4096*16 + 16*TT*16 + 16*TT*4 + 2*16*HH*4 + 16*HH*8;
    cudaFuncSetAttribute(lstm_fused, cudaFuncAttributeMaxDynamicSharedMemorySize, smemL);

    lstm_fused<<<NN/16, 256, smemL>>>(inputs, w_ih0, w_hh0, b_ih0, b_hh0,
                                      w_ih1, w_hh1, b_ih1, b_hh1);
    adj_kernel<<<dim3(NN/32, NN/32), 1024>>>(relm);
    prep1_kernel<<<NN/16, 256>>>(gat1_W, gat1_as, gat1_ad);
    gat1_agg_kernel<<<NN/8, 256>>>(gat1_b);
    prep2_kernel<<<NN/8, 256>>>(gat2_W, gat2_as, gat2_ad, gat2_b, fc_W, fc_b);
    gat2_agg_kernel<<<NN/8, 256>>>(out);
}